// round 8
// baseline (speedup 1.0000x reference)
#include <cuda_runtime.h>
#include <cuda_fp16.h>
#include <stdint.h>

#define N_NODES 50000
#define N_EDGES 625000
#define IN_DIMS 128
#define ROWS_PER_WARP 8

#define EDGE_THREADS 512
#define EDGE_GRID 152
#define EDGE_CHUNK ((N_EDGES + EDGE_GRID - 1) / EDGE_GRID)   // 4112
#define EDGE_ITERS 5                                          // ceil(4112 / (512*2))
#define TABLE_BYTES (N_NODES * 4)                             // half2 per node = 200000 B
#define HALF_TABLE (TABLE_BYTES / 2)                          // 100000 B (16B-multiple)

// Interleaved per-node table: {s = x.W_src + b, t = x.W_dst} as fp16.
__device__ __align__(16) __half2 g_st[N_NODES];

// ---------------- node pass: 8 rows per warp, loads batched for MLP ----------------
__global__ void node_dot_kernel(const float* __restrict__ x,
                                const float* __restrict__ W,
                                const float* __restrict__ b) {
    int warp = (int)((blockIdx.x * blockDim.x + threadIdx.x) >> 5);
    int lane = threadIdx.x & 31;
    int row0 = warp * ROWS_PER_WARP;
    if (row0 >= N_NODES) return;

    const float4 ws = reinterpret_cast<const float4*>(W)[lane];             // W_src
    const float4 wd = reinterpret_cast<const float4*>(W + IN_DIMS)[lane];   // W_dst
    float bias = __ldg(b);

    float4 xa[ROWS_PER_WARP];
    #pragma unroll
    for (int r = 0; r < ROWS_PER_WARP; r++) {
        int row = row0 + r;
        if (row < N_NODES)
            xa[r] = reinterpret_cast<const float4*>(x + (size_t)row * IN_DIMS)[lane];
    }

    #pragma unroll
    for (int r = 0; r < ROWS_PER_WARP; r++) {
        int row = row0 + r;
        if (row >= N_NODES) break;
        float ps = fmaf(xa[r].x, ws.x, fmaf(xa[r].y, ws.y, fmaf(xa[r].z, ws.z, xa[r].w * ws.w)));
        float pt = fmaf(xa[r].x, wd.x, fmaf(xa[r].y, wd.y, fmaf(xa[r].z, wd.z, xa[r].w * wd.w)));
        #pragma unroll
        for (int o = 16; o > 0; o >>= 1) {
            ps += __shfl_xor_sync(0xffffffffu, ps, o);
            pt += __shfl_xor_sync(0xffffffffu, pt, o);
        }
        if (lane == 0)
            g_st[row] = make_half2(__float2half_rn(ps + bias), __float2half_rn(pt));
    }
}

// ---------------- edge pass: cluster-2 multicast bulk fill + smem gather ----------------
__global__ void __launch_bounds__(EDGE_THREADS, 1) __cluster_dims__(2, 1, 1)
edge_gather_kernel(const int* __restrict__ ei,
                   float* __restrict__ out) {
    extern __shared__ __half2 st[];
    __shared__ __align__(8) uint64_t mbar;

    int tid = threadIdx.x;
    uint32_t rank;
    asm("mov.u32 %0, %%cluster_ctarank;" : "=r"(rank));

    uint32_t smem_base;
    asm("{ .reg .u64 t; cvta.to.shared.u64 t, %1; cvt.u32.u64 %0, t; }"
        : "=r"(smem_base) : "l"(st));
    uint32_t mbar_addr;
    asm("{ .reg .u64 t; cvta.to.shared.u64 t, %1; cvt.u32.u64 %0, t; }"
        : "=r"(mbar_addr) : "l"(&mbar));

    if (tid == 0) {
        asm volatile("mbarrier.init.shared.b64 [%0], %1;"
                     :: "r"(mbar_addr), "r"(1u) : "memory");
    }
    // Both CTAs' mbarriers must be initialized before any multicast targets them.
    asm volatile("barrier.cluster.arrive.aligned;" ::: "memory");
    asm volatile("barrier.cluster.wait.aligned;" ::: "memory");

    // Elected thread: expect full table, issue multicast bulk copy of OUR half
    // to BOTH CTAs. Each CTA's barrier accumulates 2 x HALF_TABLE = TABLE_BYTES.
    if (tid == 0) {
        asm volatile("mbarrier.arrive.expect_tx.shared.b64 _, [%0], %1;"
                     :: "r"(mbar_addr), "r"((uint32_t)TABLE_BYTES) : "memory");
        const char* src = reinterpret_cast<const char*>(g_st) + rank * HALF_TABLE;
        asm volatile(
            "cp.async.bulk.shared::cluster.global.mbarrier::complete_tx::bytes"
            ".multicast::cluster [%0], [%1], %2, [%3], %4;"
            :: "r"(smem_base + rank * HALF_TABLE), "l"(src),
               "r"((uint32_t)HALF_TABLE), "r"(mbar_addr), "h"((uint16_t)0x3)
            : "memory");
    }

    // Prefetch this CTA's edge indices while TMA fills smem.
    int base = (int)blockIdx.x * EDGE_CHUNK;
    int end  = min(base + EDGE_CHUNK, N_EDGES);
    int2 si[EDGE_ITERS], di[EDGE_ITERS];
    #pragma unroll
    for (int i = 0; i < EDGE_ITERS; i++) {
        int e = base + (i * EDGE_THREADS + tid) * 2;
        if (e < end) {
            si[i] = *reinterpret_cast<const int2*>(ei + e);
            di[i] = *reinterpret_cast<const int2*>(ei + N_EDGES + e);
        } else {
            si[i] = make_int2(0, 0);
            di[i] = make_int2(0, 0);
        }
    }

    // Wait for the full table (both halves, from both CTAs' multicasts).
    {
        uint32_t done;
        asm volatile(
            "{\n\t"
            ".reg .pred p;\n\t"
            "mbarrier.try_wait.parity.shared.b64 p, [%1], %2;\n\t"
            "selp.b32 %0, 1, 0, p;\n\t"
            "}"
            : "=r"(done) : "r"(mbar_addr), "r"(0u) : "memory");
        if (!done) {
            asm volatile(
                "{\n\t"
                ".reg .pred P1;\n\t"
                "WL_%=:\n\t"
                "mbarrier.try_wait.parity.shared.b64 P1, [%0], %1, 0x989680;\n\t"
                "@P1 bra.uni WD_%=;\n\t"
                "bra.uni WL_%=;\n\t"
                "WD_%=:\n\t"
                "}"
                :: "r"(mbar_addr), "r"(0u) : "memory");
        }
    }

    // Gather from smem, compute, store. (bias folded into table s-half)
    #pragma unroll
    for (int i = 0; i < EDGE_ITERS; i++) {
        int e = base + (i * EDGE_THREADS + tid) * 2;
        if (e < end) {
            __half2 a0 = st[si[i].x];
            __half2 c0 = st[di[i].x];
            __half2 a1 = st[si[i].y];
            __half2 c1 = st[di[i].y];
            float2 r;
            r.x = __low2float(a0) + __high2float(c0);
            r.y = __low2float(a1) + __high2float(c1);
            *reinterpret_cast<float2*>(out + e) = r;
        }
    }

    // No CTA may exit while its peer's multicast (targeting this CTA's smem)
    // could still be in flight relative to cluster teardown.
    asm volatile("barrier.cluster.arrive.aligned;" ::: "memory");
    asm volatile("barrier.cluster.wait.aligned;" ::: "memory");
}

extern "C" void kernel_launch(void* const* d_in, const int* in_sizes, int n_in,
                              void* d_out, int out_size) {
    const float* x   = (const float*)d_in[0];   // [N_NODES, 128] f32
    const int*   ei  = (const int*)d_in[1];     // [2, N_EDGES] int32
    const float* W   = (const float*)d_in[2];   // [1, 256] f32
    const float* b   = (const float*)d_in[3];   // [1] f32
    float*       out = (float*)d_out;           // [N_EDGES] f32

    // Idempotent attribute set (host-side config, not a stream op).
    cudaFuncSetAttribute(edge_gather_kernel,
                         cudaFuncAttributeMaxDynamicSharedMemorySize, TABLE_BYTES);

    // Node pass: 8 rows/warp, 256 threads/block.
    {
        int threads = 256;
        int warps = (N_NODES + ROWS_PER_WARP - 1) / ROWS_PER_WARP;   // 6250
        int blocks = (warps * 32 + threads - 1) / threads;           // 782
        node_dot_kernel<<<blocks, threads>>>(x, W, b);
    }
    // Edge pass: persistent, cluster-2 multicast table fill.
    edge_gather_kernel<<<EDGE_GRID, EDGE_THREADS, TABLE_BYTES>>>(ei, out);
}

// round 9
// speedup vs baseline: 1.0380x; 1.0380x over previous
#include <cuda_runtime.h>
#include <cuda_fp16.h>
#include <stdint.h>

#define N_NODES 50000
#define N_EDGES 625000
#define IN_DIMS 128
#define ROWS_PER_WARP 8

#define EDGE_THREADS 1024
#define EDGE_GRID 64
#define EDGE_CHUNK ((N_EDGES + EDGE_GRID - 1) / EDGE_GRID)   // 9766 (even)
#define EDGE_ITERS ((EDGE_CHUNK + EDGE_THREADS * 2 - 1) / (EDGE_THREADS * 2))  // 5
#define TABLE_BYTES (N_NODES * 4)                             // half2 per node = 200000 B

// Interleaved per-node table: {s = x.W_src + b, t = x.W_dst} as fp16.
__device__ __align__(16) __half2 g_st[N_NODES];

// ---------------- node pass: 8 rows per warp, loads batched for MLP ----------------
__global__ void node_dot_kernel(const float* __restrict__ x,
                                const float* __restrict__ W,
                                const float* __restrict__ b) {
    int warp = (int)((blockIdx.x * blockDim.x + threadIdx.x) >> 5);
    int lane = threadIdx.x & 31;
    int row0 = warp * ROWS_PER_WARP;
    if (row0 >= N_NODES) return;

    const float4 ws = reinterpret_cast<const float4*>(W)[lane];             // W_src
    const float4 wd = reinterpret_cast<const float4*>(W + IN_DIMS)[lane];   // W_dst
    float bias = __ldg(b);

    float4 xa[ROWS_PER_WARP];
    #pragma unroll
    for (int r = 0; r < ROWS_PER_WARP; r++) {
        int row = row0 + r;
        if (row < N_NODES)
            xa[r] = reinterpret_cast<const float4*>(x + (size_t)row * IN_DIMS)[lane];
    }

    #pragma unroll
    for (int r = 0; r < ROWS_PER_WARP; r++) {
        int row = row0 + r;
        if (row >= N_NODES) break;
        float ps = fmaf(xa[r].x, ws.x, fmaf(xa[r].y, ws.y, fmaf(xa[r].z, ws.z, xa[r].w * ws.w)));
        float pt = fmaf(xa[r].x, wd.x, fmaf(xa[r].y, wd.y, fmaf(xa[r].z, wd.z, xa[r].w * wd.w)));
        #pragma unroll
        for (int o = 16; o > 0; o >>= 1) {
            ps += __shfl_xor_sync(0xffffffffu, ps, o);
            pt += __shfl_xor_sync(0xffffffffu, pt, o);
        }
        if (lane == 0)
            g_st[row] = make_half2(__float2half_rn(ps + bias), __float2half_rn(pt));
    }
}

// ---------------- edge pass: 64 fat CTAs; fill traffic scales with grid ----------------
__global__ void __launch_bounds__(EDGE_THREADS, 1)
edge_gather_kernel(const int* __restrict__ ei,
                   float* __restrict__ out) {
    extern __shared__ __half2 st[];
    int tid = threadIdx.x;
    int base = (int)blockIdx.x * EDGE_CHUNK;
    int end  = min(base + EDGE_CHUNK, N_EDGES);

    // 1) Start the smem table fill first (cp.async: no register round-trip;
    //    retirement proceeds while we issue index loads below).
    uint32_t s_base;
    asm("{ .reg .u64 t; cvta.to.shared.u64 t, %1; cvt.u32.u64 %0, t; }"
        : "=r"(s_base) : "l"(st));
    {
        const char* g_base = reinterpret_cast<const char*>(g_st);
        const int n_chunks = TABLE_BYTES / 16;   // 12500
        #pragma unroll 4
        for (int c = tid; c < n_chunks; c += EDGE_THREADS) {
            asm volatile("cp.async.cg.shared.global [%0], [%1], 16;"
                         :: "r"(s_base + c * 16), "l"(g_base + (size_t)c * 16));
        }
        asm volatile("cp.async.commit_group;");
    }

    // 2) Prefetch this thread's edge indices (independent LDGs, overlap with fill).
    int2 si[EDGE_ITERS], di[EDGE_ITERS];
    #pragma unroll
    for (int i = 0; i < EDGE_ITERS; i++) {
        int e = base + (i * EDGE_THREADS + tid) * 2;
        if (e < end) {
            si[i] = *reinterpret_cast<const int2*>(ei + e);
            di[i] = *reinterpret_cast<const int2*>(ei + N_EDGES + e);
        } else {
            si[i] = make_int2(0, 0);
            di[i] = make_int2(0, 0);
        }
    }

    // 3) Wait for the table, then block-wide sync.
    asm volatile("cp.async.wait_group 0;" ::: "memory");
    __syncthreads();

    // 4) Gather from smem, compute, store. (bias folded into table s-half)
    #pragma unroll
    for (int i = 0; i < EDGE_ITERS; i++) {
        int e = base + (i * EDGE_THREADS + tid) * 2;
        if (e < end) {
            __half2 a0 = st[si[i].x];
            __half2 c0 = st[di[i].x];
            __half2 a1 = st[si[i].y];
            __half2 c1 = st[di[i].y];
            float2 r;
            r.x = __low2float(a0) + __high2float(c0);
            r.y = __low2float(a1) + __high2float(c1);
            *reinterpret_cast<float2*>(out + e) = r;
        }
    }
}

extern "C" void kernel_launch(void* const* d_in, const int* in_sizes, int n_in,
                              void* d_out, int out_size) {
    const float* x   = (const float*)d_in[0];   // [N_NODES, 128] f32
    const int*   ei  = (const int*)d_in[1];     // [2, N_EDGES] int32
    const float* W   = (const float*)d_in[2];   // [1, 256] f32
    const float* b   = (const float*)d_in[3];   // [1] f32
    float*       out = (float*)d_out;           // [N_EDGES] f32

    // Host-side config (not a stream op); idempotent.
    cudaFuncSetAttribute(edge_gather_kernel,
                         cudaFuncAttributeMaxDynamicSharedMemorySize, TABLE_BYTES);

    // Node pass: 8 rows/warp, 256 threads/block.
    {
        int threads = 256;
        int warps = (N_NODES + ROWS_PER_WARP - 1) / ROWS_PER_WARP;   // 6250
        int blocks = (warps * 32 + threads - 1) / threads;           // 782
        node_dot_kernel<<<blocks, threads>>>(x, W, b);
    }
    // Edge pass: 64 CTAs x 1024 threads, table staged in smem.
    edge_gather_kernel<<<EDGE_GRID, EDGE_THREADS, TABLE_BYTES>>>(ei, out);
}

// round 10
// speedup vs baseline: 1.1629x; 1.1203x over previous
#include <cuda_runtime.h>
#include <cuda_fp16.h>
#include <stdint.h>

#define N_NODES 50000
#define N_EDGES 625000
#define IN_DIMS 128
#define ROWS_PER_WARP 8

#define EDGE_THREADS 1024
#define EDGE_GRID 152
#define EDGE_CHUNK ((N_EDGES + EDGE_GRID - 1) / EDGE_GRID)                       // 4112
#define EDGE_ITERS ((EDGE_CHUNK + EDGE_THREADS * 2 - 1) / (EDGE_THREADS * 2))    // 3
#define TABLE_BYTES (N_NODES * 4)                             // half2 per node = 200000 B

// Interleaved per-node table: {s = x.W_src + b, t = x.W_dst} as fp16.
__device__ __align__(16) __half2 g_st[N_NODES];

// ---------------- node pass: 8 rows per warp, loads batched for MLP ----------------
__global__ void node_dot_kernel(const float* __restrict__ x,
                                const float* __restrict__ W,
                                const float* __restrict__ b) {
    // Fire the PDL trigger immediately: all CTAs are wave-1 resident, so the
    // dependent edge kernel launches now and prefetches its index stream
    // while we compute the table.
    cudaTriggerProgrammaticLaunchCompletion();

    int warp = (int)((blockIdx.x * blockDim.x + threadIdx.x) >> 5);
    int lane = threadIdx.x & 31;
    int row0 = warp * ROWS_PER_WARP;
    if (row0 >= N_NODES) return;

    const float4 ws = reinterpret_cast<const float4*>(W)[lane];             // W_src
    const float4 wd = reinterpret_cast<const float4*>(W + IN_DIMS)[lane];   // W_dst
    float bias = __ldg(b);

    float4 xa[ROWS_PER_WARP];
    #pragma unroll
    for (int r = 0; r < ROWS_PER_WARP; r++) {
        int row = row0 + r;
        if (row < N_NODES)
            xa[r] = reinterpret_cast<const float4*>(x + (size_t)row * IN_DIMS)[lane];
    }

    __half2 mine = make_half2(__float2half_rn(0.f), __float2half_rn(0.f));
    #pragma unroll
    for (int r = 0; r < ROWS_PER_WARP; r++) {
        int row = row0 + r;
        if (row >= N_NODES) break;
        float ps = fmaf(xa[r].x, ws.x, fmaf(xa[r].y, ws.y, fmaf(xa[r].z, ws.z, xa[r].w * ws.w)));
        float pt = fmaf(xa[r].x, wd.x, fmaf(xa[r].y, wd.y, fmaf(xa[r].z, wd.z, xa[r].w * wd.w)));
        #pragma unroll
        for (int o = 16; o > 0; o >>= 1) {
            ps += __shfl_xor_sync(0xffffffffu, ps, o);   // full butterfly: result in all lanes
            pt += __shfl_xor_sync(0xffffffffu, pt, o);
        }
        if (lane == r)
            mine = make_half2(__float2half_rn(ps + bias), __float2half_rn(pt));
    }
    // Coalesced table store: lanes 0..7 write 8 consecutive half2 (32B).
    if (lane < ROWS_PER_WARP && row0 + lane < N_NODES)
        g_st[row0 + lane] = mine;
}

// ---------------- edge pass: PDL secondary; prefetch overlaps node kernel ----------------
__global__ void __launch_bounds__(EDGE_THREADS, 1)
edge_gather_kernel(const int* __restrict__ ei,
                   float* __restrict__ out) {
    extern __shared__ __half2 st[];
    int tid = threadIdx.x;
    int base = (int)blockIdx.x * EDGE_CHUNK;
    int end  = min(base + EDGE_CHUNK, N_EDGES);

    // 1) Prefetch this thread's edge indices — independent of the node kernel,
    //    runs concurrently with it under PDL.
    int2 si[EDGE_ITERS], di[EDGE_ITERS];
    #pragma unroll
    for (int i = 0; i < EDGE_ITERS; i++) {
        int e = base + (i * EDGE_THREADS + tid) * 2;
        if (e < end) {
            si[i] = *reinterpret_cast<const int2*>(ei + e);
            di[i] = *reinterpret_cast<const int2*>(ei + N_EDGES + e);
        } else {
            si[i] = make_int2(0, 0);
            di[i] = make_int2(0, 0);
        }
    }

    // 2) Wait for the node kernel's g_st writes to be visible.
    cudaGridDependencySynchronize();

    // 3) Fill the smem table (cp.async, 16B chunks, no register round-trip).
    uint32_t s_base;
    asm("{ .reg .u64 t; cvta.to.shared.u64 t, %1; cvt.u32.u64 %0, t; }"
        : "=r"(s_base) : "l"(st));
    {
        const char* g_base = reinterpret_cast<const char*>(g_st);
        const int n_chunks = TABLE_BYTES / 16;   // 12500
        #pragma unroll 4
        for (int c = tid; c < n_chunks; c += EDGE_THREADS) {
            asm volatile("cp.async.cg.shared.global [%0], [%1], 16;"
                         :: "r"(s_base + c * 16), "l"(g_base + (size_t)c * 16));
        }
        asm volatile("cp.async.commit_group;");
        asm volatile("cp.async.wait_group 0;" ::: "memory");
    }
    __syncthreads();

    // 4) Gather from smem, compute, store. (bias folded into table s-half)
    #pragma unroll
    for (int i = 0; i < EDGE_ITERS; i++) {
        int e = base + (i * EDGE_THREADS + tid) * 2;
        if (e < end) {
            __half2 a0 = st[si[i].x];
            __half2 c0 = st[di[i].x];
            __half2 a1 = st[si[i].y];
            __half2 c1 = st[di[i].y];
            float2 r;
            r.x = __low2float(a0) + __high2float(c0);
            r.y = __low2float(a1) + __high2float(c1);
            *reinterpret_cast<float2*>(out + e) = r;
        }
    }
}

extern "C" void kernel_launch(void* const* d_in, const int* in_sizes, int n_in,
                              void* d_out, int out_size) {
    const float* x   = (const float*)d_in[0];   // [N_NODES, 128] f32
    const int*   ei  = (const int*)d_in[1];     // [2, N_EDGES] int32
    const float* W   = (const float*)d_in[2];   // [1, 256] f32
    const float* b   = (const float*)d_in[3];   // [1] f32
    float*       out = (float*)d_out;           // [N_EDGES] f32

    // Host-side config (not a stream op); idempotent.
    cudaFuncSetAttribute(edge_gather_kernel,
                         cudaFuncAttributeMaxDynamicSharedMemorySize, TABLE_BYTES);

    // Node pass: 8 rows/warp, 256 threads/block (all 782 CTAs resident in wave 1).
    {
        int threads = 256;
        int warps = (N_NODES + ROWS_PER_WARP - 1) / ROWS_PER_WARP;   // 6250
        int blocks = (warps * 32 + threads - 1) / threads;           // 782
        node_dot_kernel<<<blocks, threads>>>(x, W, b);
    }
    // Edge pass: PDL secondary — launches while node kernel runs, index
    // prefetch overlaps node compute, gridDependencySync gates the fill.
    {
        cudaLaunchConfig_t cfg = {};
        cfg.gridDim = dim3(EDGE_GRID, 1, 1);
        cfg.blockDim = dim3(EDGE_THREADS, 1, 1);
        cfg.dynamicSmemBytes = TABLE_BYTES;
        cfg.stream = 0;  // legacy default stream (same as <<<>>>)
        cudaLaunchAttribute attr[1];
        attr[0].id = cudaLaunchAttributeProgrammaticStreamSerialization;
        attr[0].val.programmaticStreamSerializationAllowed = 1;
        cfg.attrs = attr;
        cfg.numAttrs = 1;
        cudaLaunchKernelEx(&cfg, edge_gather_kernel, ei, out);
    }
}